// round 2
// baseline (speedup 1.0000x reference)
#include <cuda_runtime.h>
#include <cstdint>

// EGES model:
//   hidden[b,:] = softmax(W_weights[ci]) . { W_item_in[ci], W_side0[s0], mean_j W_side1[s1_j] }
//   out[b,c]    = sigmoid( hidden[b,:] . W_item_out[ctx[b,c],:] )
//
// Shapes: B=16384 (in_sizes[0]), D=128, K=3, S1=5, C=6.
// One warp per row; lane l owns dims [4l, 4l+4) as a float4 (512 B row, fully coalesced).

#define D4  32          // D/4 float4 per row
#define NS1 5
#define NC  6

__global__ __launch_bounds__(256)
void eges_kernel(const int* __restrict__ central,
                 const int* __restrict__ side0,
                 const int* __restrict__ side1,
                 const int* __restrict__ ctx,
                 const float4* __restrict__ Win,
                 const float4* __restrict__ Wout,
                 const float* __restrict__ Ww,
                 const float4* __restrict__ Ws0,
                 const float4* __restrict__ Ws1,
                 float* __restrict__ out,
                 int B)
{
    const int warp = (blockIdx.x * blockDim.x + threadIdx.x) >> 5;
    const int lane = threadIdx.x & 31;
    if (warp >= B) return;
    const int b = warp;

    // ---- index loads (uniform within warp; L1 broadcast) ----
    const int ci = central[b];
    const int i0 = side0[b];
    int i1[NS1];
#pragma unroll
    for (int j = 0; j < NS1; ++j) i1[j] = side1[b * NS1 + j];
    int cc[NC];
#pragma unroll
    for (int j = 0; j < NC; ++j) cc[j] = ctx[b * NC + j];

    // ---- front-batch ALL 13 row gathers (max MLP to hide DRAM latency) ----
    const float4 item = Win[(size_t)ci * D4 + lane];
    const float4 e0   = Ws0[(size_t)i0 * D4 + lane];
    float4 s1v[NS1];
#pragma unroll
    for (int j = 0; j < NS1; ++j) s1v[j] = Ws1[(size_t)i1[j] * D4 + lane];
    float4 ov[NC];
#pragma unroll
    for (int j = 0; j < NC; ++j) ov[j] = Wout[(size_t)cc[j] * D4 + lane];

    // softmax weights (3 scalars, same address across warp -> L1 broadcast)
    const float w0r = Ww[(size_t)ci * 3 + 0];
    const float w1r = Ww[(size_t)ci * 3 + 1];
    const float w2r = Ww[(size_t)ci * 3 + 2];

    // ---- mean of side1 ----
    float4 e1;
    e1.x = (s1v[0].x + s1v[1].x + s1v[2].x + s1v[3].x + s1v[4].x) * 0.2f;
    e1.y = (s1v[0].y + s1v[1].y + s1v[2].y + s1v[3].y + s1v[4].y) * 0.2f;
    e1.z = (s1v[0].z + s1v[1].z + s1v[2].z + s1v[3].z + s1v[4].z) * 0.2f;
    e1.w = (s1v[0].w + s1v[1].w + s1v[2].w + s1v[3].w + s1v[4].w) * 0.2f;

    // ---- stable softmax over 3 weights ----
    const float m  = fmaxf(w0r, fmaxf(w1r, w2r));
    const float x0 = __expf(w0r - m), x1 = __expf(w1r - m), x2 = __expf(w2r - m);
    const float inv = 1.0f / (x0 + x1 + x2);
    const float w0 = x0 * inv, w1 = x1 * inv, w2 = x2 * inv;

    // ---- hidden = w0*item + w1*e0 + w2*e1 ----
    float4 h;
    h.x = w0 * item.x + w1 * e0.x + w2 * e1.x;
    h.y = w0 * item.y + w1 * e0.y + w2 * e1.y;
    h.z = w0 * item.z + w1 * e0.z + w2 * e1.z;
    h.w = w0 * item.w + w1 * e0.w + w2 * e1.w;

    // ---- 6 context dot products, interleaved butterfly reductions ----
    float d[NC];
#pragma unroll
    for (int c = 0; c < NC; ++c)
        d[c] = h.x * ov[c].x + h.y * ov[c].y + h.z * ov[c].z + h.w * ov[c].w;

#pragma unroll
    for (int off = 16; off > 0; off >>= 1) {
#pragma unroll
        for (int c = 0; c < NC; ++c)
            d[c] += __shfl_xor_sync(0xFFFFFFFFu, d[c], off);
    }

    if (lane < NC)
        ;  // (per-lane scatter variant not used; see below)
#pragma unroll
    for (int c = 0; c < NC; ++c) {
        if (lane == 0)
            out[(size_t)b * NC + c] = 1.0f / (1.0f + __expf(-d[c]));
    }
}

extern "C" void kernel_launch(void* const* d_in, const int* in_sizes, int n_in,
                              void* d_out, int out_size)
{
    const int*    central = (const int*)d_in[0];
    const int*    side0   = (const int*)d_in[1];
    const int*    side1   = (const int*)d_in[2];
    const int*    ctx     = (const int*)d_in[3];
    const float4* Win     = (const float4*)d_in[4];
    const float4* Wout    = (const float4*)d_in[5];
    const float*  Ww      = (const float*)d_in[6];
    const float4* Ws0     = (const float4*)d_in[7];
    const float4* Ws1     = (const float4*)d_in[8];
    float* out = (float*)d_out;

    const int B = in_sizes[0];
    const int warps_per_block = 256 / 32;         // 8 warps
    const int blocks = (B + warps_per_block - 1) / warps_per_block;
    eges_kernel<<<blocks, 256>>>(central, side0, side1, ctx,
                                 Win, Wout, Ww, Ws0, Ws1, out, B);
}